// round 7
// baseline (speedup 1.0000x reference)
#include <cuda_runtime.h>
#include <cstdint>

// Problem constants
constexpr int Bn   = 8;
constexpr int Cn   = 512;
constexpr int Tn   = 1024;
constexpr int NG   = 32;
constexpr int CPG  = Cn / NG;
constexpr int NH   = 8;
constexpr int CH   = 64;
constexpr float EPSV = 1e-5f;

// Scratch (device globals: allocation-free rule)
__device__ float g_h  [Bn * Cn   * Tn];
__device__ float g_qkv[Bn * 1536 * Tn];
__device__ float g_a  [Bn * Cn   * Tn];

// ---------------------------------------------------------------------------
// bf16 helpers: pack two fp32 into one bf16x2 word (lo = lower-k element)
// ---------------------------------------------------------------------------
__device__ __forceinline__ uint32_t bfpack(float lo, float hi) {
    uint32_t r;
    asm("cvt.rn.bf16x2.f32 %0, %1, %2;" : "=r"(r) : "f"(hi), "f"(lo));
    return r;
}

// D += A(16x16 row) * B(16x8 col);  fp32 accum, bf16 inputs
__device__ __forceinline__ void mma_bf16(float* c,
    uint32_t a0, uint32_t a1, uint32_t a2, uint32_t a3,
    uint32_t b0, uint32_t b1)
{
    asm volatile(
        "mma.sync.aligned.m16n8k16.row.col.f32.bf16.bf16.f32 "
        "{%0,%1,%2,%3}, {%4,%5,%6,%7}, {%8,%9}, {%0,%1,%2,%3};\n"
        : "+f"(c[0]), "+f"(c[1]), "+f"(c[2]), "+f"(c[3])
        : "r"(a0), "r"(a1), "r"(a2), "r"(a3), "r"(b0), "r"(b1));
}

// ---------------------------------------------------------------------------
// GroupNorm, float4 I/O (HBM-bound)
// ---------------------------------------------------------------------------
__global__ __launch_bounds__(256) void gn_kernel(
    const float* __restrict__ x, const float* __restrict__ gamma,
    const float* __restrict__ beta, float* __restrict__ out)
{
    int bg = blockIdx.x;
    int b = bg >> 5, g = bg & 31;
    const int CNT4 = CPG * Tn / 4;   // 4096 float4
    size_t base = ((size_t)b * Cn + g * CPG) * Tn;
    const float4* x4 = (const float4*)(x + base);
    float4* o4 = (float4*)(out + base);

    float s = 0.f, s2 = 0.f;
    for (int i = threadIdx.x; i < CNT4; i += 256) {
        float4 v = x4[i];
        s  += v.x + v.y + v.z + v.w;
        s2 += v.x * v.x + v.y * v.y + v.z * v.z + v.w * v.w;
    }
    #pragma unroll
    for (int o = 16; o > 0; o >>= 1) {
        s  += __shfl_down_sync(0xffffffffu, s,  o);
        s2 += __shfl_down_sync(0xffffffffu, s2, o);
    }
    __shared__ float ws[8], ws2[8], sMean, sRinv;
    int wid = threadIdx.x >> 5, lane = threadIdx.x & 31;
    if (lane == 0) { ws[wid] = s; ws2[wid] = s2; }
    __syncthreads();
    if (threadIdx.x == 0) {
        float ts = 0.f, ts2 = 0.f;
        #pragma unroll
        for (int i = 0; i < 8; i++) { ts += ws[i]; ts2 += ws2[i]; }
        float mean = ts / (CPG * Tn);
        float var  = ts2 / (CPG * Tn) - mean * mean;
        sMean = mean;
        sRinv = rsqrtf(var + EPSV);
    }
    __syncthreads();
    float mean = sMean, rinv = sRinv;
    for (int i = threadIdx.x; i < CNT4; i += 256) {
        int c = g * CPG + (i >> 8);      // 256 float4 per channel row
        float ga = gamma[c] * rinv, be = beta[c] - mean * gamma[c] * rinv;
        float4 v = x4[i];
        o4[i] = make_float4(v.x * ga + be, v.y * ga + be,
                            v.z * ga + be, v.w * ga + be);
    }
}

// ---------------------------------------------------------------------------
// bf16 tensor-core SGEMM, double-buffered pipeline (unchanged from R6).
// ---------------------------------------------------------------------------
constexpr int WS_W = 20;
constexpr int XS_W = 136;

__global__ __launch_bounds__(256, 2) void sgemm_bf16(
    const float* __restrict__ W, const float* __restrict__ X,
    const float* __restrict__ bias, const float* __restrict__ resid,
    float* __restrict__ out, int O, int C, int T)
{
    __shared__ uint32_t Ws[2][128 * WS_W];
    __shared__ uint32_t Xs[2][16 * XS_W];

    int b  = blockIdx.z;
    const float* Xb = X + (size_t)b * C * T;
    float* outb     = out + (size_t)b * O * T;
    const float* rb = resid ? resid + (size_t)b * O * T : nullptr;
    int m0 = blockIdx.y * 128, n0 = blockIdx.x * 128;

    int tid = threadIdx.x, warp = tid >> 5, lane = tid & 31;
    int gid = lane >> 2, tig = lane & 3;
    int wm = warp >> 1;
    int wn = warp & 1;

    int wm_e = tid >> 2,  wk_e = (tid & 3) * 8;
    int xk2_e = tid >> 5, xn_e = (tid & 31) * 4;

    float acc[2][8][4];
    #pragma unroll
    for (int mt = 0; mt < 2; mt++)
        #pragma unroll
        for (int nt = 0; nt < 8; nt++)
            #pragma unroll
            for (int q = 0; q < 4; q++) acc[mt][nt][q] = 0.f;

    float4 w00 = *(const float4*)&W[(size_t)(m0 + wm_e     ) * C + wk_e];
    float4 w01 = *(const float4*)&W[(size_t)(m0 + wm_e     ) * C + wk_e + 4];
    float4 w10 = *(const float4*)&W[(size_t)(m0 + wm_e + 64) * C + wk_e];
    float4 w11 = *(const float4*)&W[(size_t)(m0 + wm_e + 64) * C + wk_e + 4];
    float4 x00 = *(const float4*)&Xb[(size_t)(2 * xk2_e     ) * T + n0 + xn_e];
    float4 x01 = *(const float4*)&Xb[(size_t)(2 * xk2_e  + 1) * T + n0 + xn_e];
    float4 x10 = *(const float4*)&Xb[(size_t)(2 * xk2_e + 16) * T + n0 + xn_e];
    float4 x11 = *(const float4*)&Xb[(size_t)(2 * xk2_e + 17) * T + n0 + xn_e];

    int nk = C >> 5;
    for (int i = 0; i < nk; i++) {
        int p = i & 1;
        *(uint4*)&Ws[p][wm_e * WS_W + (wk_e >> 1)] =
            make_uint4(bfpack(w00.x, w00.y), bfpack(w00.z, w00.w),
                       bfpack(w01.x, w01.y), bfpack(w01.z, w01.w));
        *(uint4*)&Ws[p][(wm_e + 64) * WS_W + (wk_e >> 1)] =
            make_uint4(bfpack(w10.x, w10.y), bfpack(w10.z, w10.w),
                       bfpack(w11.x, w11.y), bfpack(w11.z, w11.w));
        *(uint4*)&Xs[p][xk2_e * XS_W + xn_e] =
            make_uint4(bfpack(x00.x, x01.x), bfpack(x00.y, x01.y),
                       bfpack(x00.z, x01.z), bfpack(x00.w, x01.w));
        *(uint4*)&Xs[p][(xk2_e + 8) * XS_W + xn_e] =
            make_uint4(bfpack(x10.x, x11.x), bfpack(x10.y, x11.y),
                       bfpack(x10.z, x11.z), bfpack(x10.w, x11.w));
        __syncthreads();

        if (i + 1 < nk) {
            int k0 = (i + 1) << 5;
            w00 = *(const float4*)&W[(size_t)(m0 + wm_e     ) * C + k0 + wk_e];
            w01 = *(const float4*)&W[(size_t)(m0 + wm_e     ) * C + k0 + wk_e + 4];
            w10 = *(const float4*)&W[(size_t)(m0 + wm_e + 64) * C + k0 + wk_e];
            w11 = *(const float4*)&W[(size_t)(m0 + wm_e + 64) * C + k0 + wk_e + 4];
            x00 = *(const float4*)&Xb[(size_t)(k0 + 2 * xk2_e     ) * T + n0 + xn_e];
            x01 = *(const float4*)&Xb[(size_t)(k0 + 2 * xk2_e  + 1) * T + n0 + xn_e];
            x10 = *(const float4*)&Xb[(size_t)(k0 + 2 * xk2_e + 16) * T + n0 + xn_e];
            x11 = *(const float4*)&Xb[(size_t)(k0 + 2 * xk2_e + 17) * T + n0 + xn_e];
        }

        #pragma unroll
        for (int kh = 0; kh < 2; kh++) {
            int kho = kh * 8;
            uint32_t a[2][4];
            #pragma unroll
            for (int mt = 0; mt < 2; mt++) {
                int rbse = wm * 32 + mt * 16;
                a[mt][0] = Ws[p][(rbse + gid    ) * WS_W + kho + tig    ];
                a[mt][1] = Ws[p][(rbse + gid + 8) * WS_W + kho + tig    ];
                a[mt][2] = Ws[p][(rbse + gid    ) * WS_W + kho + tig + 4];
                a[mt][3] = Ws[p][(rbse + gid + 8) * WS_W + kho + tig + 4];
            }
            #pragma unroll
            for (int nt = 0; nt < 8; nt++) {
                int cb = wn * 64 + nt * 8;
                uint32_t b0 = Xs[p][(kho + tig    ) * XS_W + cb + gid];
                uint32_t b1 = Xs[p][(kho + tig + 4) * XS_W + cb + gid];
                #pragma unroll
                for (int mt = 0; mt < 2; mt++)
                    mma_bf16(acc[mt][nt], a[mt][0], a[mt][1], a[mt][2], a[mt][3], b0, b1);
            }
        }
    }

    #pragma unroll
    for (int mt = 0; mt < 2; mt++) {
        #pragma unroll
        for (int rr = 0; rr < 2; rr++) {
            int m = m0 + wm * 32 + mt * 16 + gid + rr * 8;
            float bi = bias[m];
            #pragma unroll
            for (int nt = 0; nt < 8; nt++) {
                int n = n0 + wn * 64 + nt * 8 + 2 * tig;
                float v0 = acc[mt][nt][rr * 2 + 0] + bi;
                float v1 = acc[mt][nt][rr * 2 + 1] + bi;
                if (rb) {
                    v0 += rb[(size_t)m * T + n];
                    v1 += rb[(size_t)m * T + n + 1];
                }
                *(float2*)&outb[(size_t)m * T + n] = make_float2(v0, v1);
            }
        }
    }
}

// ---------------------------------------------------------------------------
// Flash attention, bf16 m16n8k16, 64-wide key tiles (16 iters), 3 CTAs/SM.
// P stays in REGISTERS: the S accumulator fragment layout equals the PV
// A-fragment layout, so P is packed via cvt.rn.bf16x2 straight into MMAs.
// SMEM (packed bf16x2 words, all fragment accesses conflict-free):
//   Qs[i][c2]  stride 36  (a-frag addr ≡ 4*gid+tig mod 32)
//   Ks[c2][j]  stride 72  (b-frag addr ≡ 8*tig+gid mod 32)
//   Vs[c][j2]  stride 36  (b-frag addr ≡ 4*gid+tig mod 32)
// ---------------------------------------------------------------------------
constexpr int QS_W = 36;
constexpr int KS_W = 72;
constexpr int VS_W = 36;

constexpr int ATTN_SMEM_WORDS = 128 * QS_W + 32 * KS_W + 64 * VS_W;  // 9216
constexpr int ATTN_SMEM_BYTES = ATTN_SMEM_WORDS * 4;                 // 36,864

__global__ __launch_bounds__(256, 3) void attn_kernel(
    const float* __restrict__ qkv, float* __restrict__ a_out)
{
    extern __shared__ uint32_t sm[];
    uint32_t* Qs = sm;                       // [i][c2]
    uint32_t* Ks = Qs + 128 * QS_W;          // [c2][j]
    uint32_t* Vs = Ks + 32 * KS_W;           // [c][j2]

    int blk = blockIdx.x;
    int qt = blk & 7, hh = blk >> 3;
    int b = hh >> 3, h = hh & 7;
    const float* qb = qkv + ((size_t)b * 1536 + h * 192) * Tn;
    const float* kb = qb + 64 * Tn;
    const float* vb = qb + 128 * Tn;
    int i0 = qt * 128;

    int tid = threadIdx.x, warp = tid >> 5, lane = tid & 31;
    int gid = lane >> 2, tig = lane & 3;
    int rA = warp * 16 + gid;        // first row; second is rA + 8

    // load Q packed: Qs[i][c2] = bf16x2(q[2c2][i], q[2c2+1][i]) * 0.125
    #pragma unroll 4
    for (int e = tid; e < 32 * 128; e += 256) {
        int i = e & 127, c2 = e >> 7;
        float lo = qb[(size_t)(2 * c2    ) * Tn + i0 + i] * 0.125f;
        float hi = qb[(size_t)(2 * c2 + 1) * Tn + i0 + i] * 0.125f;
        Qs[i * QS_W + c2] = bfpack(lo, hi);
    }

    float mrow0 = -1e30f, mrow1 = -1e30f;
    float lrow0 = 0.f, lrow1 = 0.f;
    float oacc[8][4];
    #pragma unroll
    for (int nt = 0; nt < 8; nt++)
        #pragma unroll
        for (int q = 0; q < 4; q++) oacc[nt][q] = 0.f;

    for (int s0 = 0; s0 < Tn; s0 += 64) {
        __syncthreads();   // everyone done with previous K/V tile
        // stage K: Ks[c2][j], 64 keys
        #pragma unroll 2
        for (int e = tid; e < 32 * 64; e += 256) {
            int j = e & 63, c2 = e >> 6;
            Ks[c2 * KS_W + j] = bfpack(kb[(size_t)(2 * c2    ) * Tn + s0 + j],
                                       kb[(size_t)(2 * c2 + 1) * Tn + s0 + j]);
        }
        // stage V: Vs[c][j2]
        #pragma unroll 2
        for (int e = tid; e < 64 * 16; e += 256) {
            int j4 = e & 15, c = e >> 4;
            float4 v = *(const float4*)&vb[(size_t)c * Tn + s0 + 4 * j4];
            Vs[c * VS_W + 2 * j4    ] = bfpack(v.x, v.y);
            Vs[c * VS_W + 2 * j4 + 1] = bfpack(v.z, v.w);
        }
        __syncthreads();

        // ---- S = Q^T K : rows [warp*16,+16), cols 0..63 ----
        float sacc[8][4];
        #pragma unroll
        for (int nt = 0; nt < 8; nt++)
            #pragma unroll
            for (int q = 0; q < 4; q++) sacc[nt][q] = 0.f;

        #pragma unroll
        for (int c2o = 0; c2o < 32; c2o += 8) {
            uint32_t a0 = Qs[(rA    ) * QS_W + c2o + tig    ];
            uint32_t a1 = Qs[(rA + 8) * QS_W + c2o + tig    ];
            uint32_t a2 = Qs[(rA    ) * QS_W + c2o + tig + 4];
            uint32_t a3 = Qs[(rA + 8) * QS_W + c2o + tig + 4];
            #pragma unroll
            for (int nt = 0; nt < 8; nt++) {
                uint32_t b0 = Ks[(c2o + tig    ) * KS_W + nt * 8 + gid];
                uint32_t b1 = Ks[(c2o + tig + 4) * KS_W + nt * 8 + gid];
                mma_bf16(sacc[nt], a0, a1, a2, a3, b0, b1);
            }
        }

        // ---- online softmax (rows rA and rA+8; reduce across quad) ----
        float mx0 = -1e30f, mx1 = -1e30f;
        #pragma unroll
        for (int nt = 0; nt < 8; nt++) {
            mx0 = fmaxf(mx0, fmaxf(sacc[nt][0], sacc[nt][1]));
            mx1 = fmaxf(mx1, fmaxf(sacc[nt][2], sacc[nt][3]));
        }
        mx0 = fmaxf(mx0, __shfl_xor_sync(0xffffffffu, mx0, 1));
        mx0 = fmaxf(mx0, __shfl_xor_sync(0xffffffffu, mx0, 2));
        mx1 = fmaxf(mx1, __shfl_xor_sync(0xffffffffu, mx1, 1));
        mx1 = fmaxf(mx1, __shfl_xor_sync(0xffffffffu, mx1, 2));
        float mn0 = fmaxf(mrow0, mx0), mn1 = fmaxf(mrow1, mx1);
        float corr0 = __expf(mrow0 - mn0), corr1 = __expf(mrow1 - mn1);
        mrow0 = mn0; mrow1 = mn1;

        float rs0 = 0.f, rs1 = 0.f;
        #pragma unroll
        for (int nt = 0; nt < 8; nt++) {
            sacc[nt][0] = __expf(sacc[nt][0] - mn0);
            sacc[nt][1] = __expf(sacc[nt][1] - mn0);
            sacc[nt][2] = __expf(sacc[nt][2] - mn1);
            sacc[nt][3] = __expf(sacc[nt][3] - mn1);
            rs0 += sacc[nt][0] + sacc[nt][1];
            rs1 += sacc[nt][2] + sacc[nt][3];
        }
        rs0 += __shfl_xor_sync(0xffffffffu, rs0, 1);
        rs0 += __shfl_xor_sync(0xffffffffu, rs0, 2);
        rs1 += __shfl_xor_sync(0xffffffffu, rs1, 1);
        rs1 += __shfl_xor_sync(0xffffffffu, rs1, 2);
        lrow0 = lrow0 * corr0 + rs0;
        lrow1 = lrow1 * corr1 + rs1;
        #pragma unroll
        for (int nt = 0; nt < 8; nt++) {
            oacc[nt][0] *= corr0; oacc[nt][1] *= corr0;
            oacc[nt][2] *= corr1; oacc[nt][3] *= corr1;
        }

        // ---- O += P * V : P packed from sacc registers (no SMEM!) ----
        #pragma unroll
        for (int kbk = 0; kbk < 4; kbk++) {
            uint32_t a0 = bfpack(sacc[2 * kbk    ][0], sacc[2 * kbk    ][1]);
            uint32_t a1 = bfpack(sacc[2 * kbk    ][2], sacc[2 * kbk    ][3]);
            uint32_t a2 = bfpack(sacc[2 * kbk + 1][0], sacc[2 * kbk + 1][1]);
            uint32_t a3 = bfpack(sacc[2 * kbk + 1][2], sacc[2 * kbk + 1][3]);
            #pragma unroll
            for (int nt = 0; nt < 8; nt++) {
                uint32_t b0 = Vs[(nt * 8 + gid) * VS_W + 8 * kbk + tig    ];
                uint32_t b1 = Vs[(nt * 8 + gid) * VS_W + 8 * kbk + tig + 4];
                mma_bf16(oacc[nt], a0, a1, a2, a3, b0, b1);
            }
        }
    }

    // epilogue: a[b][h*64+c][i0+i] = oacc / l
    float inv0 = 1.f / lrow0, inv1 = 1.f / lrow1;
    size_t obase = ((size_t)b * Cn + h * CH) * Tn + i0;
    #pragma unroll
    for (int nt = 0; nt < 8; nt++) {
        int c = nt * 8 + 2 * tig;
        a_out[obase + (size_t)(c    ) * Tn + rA    ] = oacc[nt][0] * inv0;
        a_out[obase + (size_t)(c + 1) * Tn + rA    ] = oacc[nt][1] * inv0;
        a_out[obase + (size_t)(c    ) * Tn + rA + 8] = oacc[nt][2] * inv1;
        a_out[obase + (size_t)(c + 1) * Tn + rA + 8] = oacc[nt][3] * inv1;
    }
}

// ---------------------------------------------------------------------------
extern "C" void kernel_launch(void* const* d_in, const int* in_sizes, int n_in,
                              void* d_out, int out_size)
{
    const float* x      = (const float*)d_in[0];
    const float* gamma  = (const float*)d_in[1];
    const float* beta   = (const float*)d_in[2];
    const float* w_qkv  = (const float*)d_in[3];
    const float* b_qkv  = (const float*)d_in[4];
    const float* w_proj = (const float*)d_in[5];
    const float* b_proj = (const float*)d_in[6];
    float* out = (float*)d_out;

    float *h_ptr, *qkv_ptr, *a_ptr;
    cudaGetSymbolAddress((void**)&h_ptr,   g_h);
    cudaGetSymbolAddress((void**)&qkv_ptr, g_qkv);
    cudaGetSymbolAddress((void**)&a_ptr,   g_a);

    cudaFuncSetAttribute(attn_kernel,
                         cudaFuncAttributeMaxDynamicSharedMemorySize,
                         ATTN_SMEM_BYTES);

    // 1. GroupNorm
    gn_kernel<<<Bn * NG, 256>>>(x, gamma, beta, h_ptr);

    // 2. QKV GEMM (bf16 tensor cores, pipelined)
    sgemm_bf16<<<dim3(Tn / 128, 1536 / 128, Bn), 256>>>(
        w_qkv, h_ptr, b_qkv, nullptr, qkv_ptr, 1536, Cn, Tn);

    // 3. Attention (bf16, register-P, 3 CTAs/SM)
    attn_kernel<<<Bn * NH * (Tn / 128), 256, ATTN_SMEM_BYTES>>>(qkv_ptr, a_ptr);

    // 4. Proj GEMM + bias + residual
    sgemm_bf16<<<dim3(Tn / 128, Cn / 128, Bn), 256>>>(
        w_proj, a_ptr, b_proj, x, out, Cn, Cn, Tn);
}

// round 8
// speedup vs baseline: 1.1088x; 1.1088x over previous
#include <cuda_runtime.h>
#include <cstdint>

// Problem constants
constexpr int Bn   = 8;
constexpr int Cn   = 512;
constexpr int Tn   = 1024;
constexpr int NG   = 32;
constexpr int CPG  = Cn / NG;
constexpr int NH   = 8;
constexpr int CH   = 64;
constexpr float EPSV = 1e-5f;
constexpr float LOG2E = 1.4426950408889634f;

// Scratch (device globals: allocation-free rule)
__device__ float g_h  [Bn * Cn   * Tn];
__device__ float g_qkv[Bn * 1536 * Tn];
__device__ float g_a  [Bn * Cn   * Tn];

// ---------------------------------------------------------------------------
// bf16 helpers
// ---------------------------------------------------------------------------
__device__ __forceinline__ uint32_t bfpack(float lo, float hi) {
    uint32_t r;
    asm("cvt.rn.bf16x2.f32 %0, %1, %2;" : "=r"(r) : "f"(hi), "f"(lo));
    return r;
}

__device__ __forceinline__ void mma_bf16(float* c,
    uint32_t a0, uint32_t a1, uint32_t a2, uint32_t a3,
    uint32_t b0, uint32_t b1)
{
    asm volatile(
        "mma.sync.aligned.m16n8k16.row.col.f32.bf16.bf16.f32 "
        "{%0,%1,%2,%3}, {%4,%5,%6,%7}, {%8,%9}, {%0,%1,%2,%3};\n"
        : "+f"(c[0]), "+f"(c[1]), "+f"(c[2]), "+f"(c[3])
        : "r"(a0), "r"(a1), "r"(a2), "r"(a3), "r"(b0), "r"(b1));
}

// no-op spacer so ncu's "-s 5 -c 1" captures attn_kernel (launch #6)
__global__ void nop_kernel() {}

// ---------------------------------------------------------------------------
// GroupNorm, float4 I/O
// ---------------------------------------------------------------------------
__global__ __launch_bounds__(256) void gn_kernel(
    const float* __restrict__ x, const float* __restrict__ gamma,
    const float* __restrict__ beta, float* __restrict__ out)
{
    int bg = blockIdx.x;
    int b = bg >> 5, g = bg & 31;
    const int CNT4 = CPG * Tn / 4;
    size_t base = ((size_t)b * Cn + g * CPG) * Tn;
    const float4* x4 = (const float4*)(x + base);
    float4* o4 = (float4*)(out + base);

    float s = 0.f, s2 = 0.f;
    for (int i = threadIdx.x; i < CNT4; i += 256) {
        float4 v = x4[i];
        s  += v.x + v.y + v.z + v.w;
        s2 += v.x * v.x + v.y * v.y + v.z * v.z + v.w * v.w;
    }
    #pragma unroll
    for (int o = 16; o > 0; o >>= 1) {
        s  += __shfl_down_sync(0xffffffffu, s,  o);
        s2 += __shfl_down_sync(0xffffffffu, s2, o);
    }
    __shared__ float ws[8], ws2[8], sMean, sRinv;
    int wid = threadIdx.x >> 5, lane = threadIdx.x & 31;
    if (lane == 0) { ws[wid] = s; ws2[wid] = s2; }
    __syncthreads();
    if (threadIdx.x == 0) {
        float ts = 0.f, ts2 = 0.f;
        #pragma unroll
        for (int i = 0; i < 8; i++) { ts += ws[i]; ts2 += ws2[i]; }
        float mean = ts / (CPG * Tn);
        float var  = ts2 / (CPG * Tn) - mean * mean;
        sMean = mean;
        sRinv = rsqrtf(var + EPSV);
    }
    __syncthreads();
    float mean = sMean, rinv = sRinv;
    for (int i = threadIdx.x; i < CNT4; i += 256) {
        int c = g * CPG + (i >> 8);
        float ga = gamma[c] * rinv, be = beta[c] - mean * gamma[c] * rinv;
        float4 v = x4[i];
        o4[i] = make_float4(v.x * ga + be, v.y * ga + be,
                            v.z * ga + be, v.w * ga + be);
    }
}

// ---------------------------------------------------------------------------
// bf16 tensor-core SGEMM, double-buffered pipeline (unchanged).
// ---------------------------------------------------------------------------
constexpr int WS_W = 20;
constexpr int XS_W = 136;

__global__ __launch_bounds__(256, 2) void sgemm_bf16(
    const float* __restrict__ W, const float* __restrict__ X,
    const float* __restrict__ bias, const float* __restrict__ resid,
    float* __restrict__ out, int O, int C, int T)
{
    __shared__ uint32_t Ws[2][128 * WS_W];
    __shared__ uint32_t Xs[2][16 * XS_W];

    int b  = blockIdx.z;
    const float* Xb = X + (size_t)b * C * T;
    float* outb     = out + (size_t)b * O * T;
    const float* rb = resid ? resid + (size_t)b * O * T : nullptr;
    int m0 = blockIdx.y * 128, n0 = blockIdx.x * 128;

    int tid = threadIdx.x, warp = tid >> 5, lane = tid & 31;
    int gid = lane >> 2, tig = lane & 3;
    int wm = warp >> 1;
    int wn = warp & 1;

    int wm_e = tid >> 2,  wk_e = (tid & 3) * 8;
    int xk2_e = tid >> 5, xn_e = (tid & 31) * 4;

    float acc[2][8][4];
    #pragma unroll
    for (int mt = 0; mt < 2; mt++)
        #pragma unroll
        for (int nt = 0; nt < 8; nt++)
            #pragma unroll
            for (int q = 0; q < 4; q++) acc[mt][nt][q] = 0.f;

    float4 w00 = *(const float4*)&W[(size_t)(m0 + wm_e     ) * C + wk_e];
    float4 w01 = *(const float4*)&W[(size_t)(m0 + wm_e     ) * C + wk_e + 4];
    float4 w10 = *(const float4*)&W[(size_t)(m0 + wm_e + 64) * C + wk_e];
    float4 w11 = *(const float4*)&W[(size_t)(m0 + wm_e + 64) * C + wk_e + 4];
    float4 x00 = *(const float4*)&Xb[(size_t)(2 * xk2_e     ) * T + n0 + xn_e];
    float4 x01 = *(const float4*)&Xb[(size_t)(2 * xk2_e  + 1) * T + n0 + xn_e];
    float4 x10 = *(const float4*)&Xb[(size_t)(2 * xk2_e + 16) * T + n0 + xn_e];
    float4 x11 = *(const float4*)&Xb[(size_t)(2 * xk2_e + 17) * T + n0 + xn_e];

    int nk = C >> 5;
    for (int i = 0; i < nk; i++) {
        int p = i & 1;
        *(uint4*)&Ws[p][wm_e * WS_W + (wk_e >> 1)] =
            make_uint4(bfpack(w00.x, w00.y), bfpack(w00.z, w00.w),
                       bfpack(w01.x, w01.y), bfpack(w01.z, w01.w));
        *(uint4*)&Ws[p][(wm_e + 64) * WS_W + (wk_e >> 1)] =
            make_uint4(bfpack(w10.x, w10.y), bfpack(w10.z, w10.w),
                       bfpack(w11.x, w11.y), bfpack(w11.z, w11.w));
        *(uint4*)&Xs[p][xk2_e * XS_W + xn_e] =
            make_uint4(bfpack(x00.x, x01.x), bfpack(x00.y, x01.y),
                       bfpack(x00.z, x01.z), bfpack(x00.w, x01.w));
        *(uint4*)&Xs[p][(xk2_e + 8) * XS_W + xn_e] =
            make_uint4(bfpack(x10.x, x11.x), bfpack(x10.y, x11.y),
                       bfpack(x10.z, x11.z), bfpack(x10.w, x11.w));
        __syncthreads();

        if (i + 1 < nk) {
            int k0 = (i + 1) << 5;
            w00 = *(const float4*)&W[(size_t)(m0 + wm_e     ) * C + k0 + wk_e];
            w01 = *(const float4*)&W[(size_t)(m0 + wm_e     ) * C + k0 + wk_e + 4];
            w10 = *(const float4*)&W[(size_t)(m0 + wm_e + 64) * C + k0 + wk_e];
            w11 = *(const float4*)&W[(size_t)(m0 + wm_e + 64) * C + k0 + wk_e + 4];
            x00 = *(const float4*)&Xb[(size_t)(k0 + 2 * xk2_e     ) * T + n0 + xn_e];
            x01 = *(const float4*)&Xb[(size_t)(k0 + 2 * xk2_e  + 1) * T + n0 + xn_e];
            x10 = *(const float4*)&Xb[(size_t)(k0 + 2 * xk2_e + 16) * T + n0 + xn_e];
            x11 = *(const float4*)&Xb[(size_t)(k0 + 2 * xk2_e + 17) * T + n0 + xn_e];
        }

        #pragma unroll
        for (int kh = 0; kh < 2; kh++) {
            int kho = kh * 8;
            uint32_t a[2][4];
            #pragma unroll
            for (int mt = 0; mt < 2; mt++) {
                int rbse = wm * 32 + mt * 16;
                a[mt][0] = Ws[p][(rbse + gid    ) * WS_W + kho + tig    ];
                a[mt][1] = Ws[p][(rbse + gid + 8) * WS_W + kho + tig    ];
                a[mt][2] = Ws[p][(rbse + gid    ) * WS_W + kho + tig + 4];
                a[mt][3] = Ws[p][(rbse + gid + 8) * WS_W + kho + tig + 4];
            }
            #pragma unroll
            for (int nt = 0; nt < 8; nt++) {
                int cb = wn * 64 + nt * 8;
                uint32_t b0 = Xs[p][(kho + tig    ) * XS_W + cb + gid];
                uint32_t b1 = Xs[p][(kho + tig + 4) * XS_W + cb + gid];
                #pragma unroll
                for (int mt = 0; mt < 2; mt++)
                    mma_bf16(acc[mt][nt], a[mt][0], a[mt][1], a[mt][2], a[mt][3], b0, b1);
            }
        }
    }

    #pragma unroll
    for (int mt = 0; mt < 2; mt++) {
        #pragma unroll
        for (int rr = 0; rr < 2; rr++) {
            int m = m0 + wm * 32 + mt * 16 + gid + rr * 8;
            float bi = bias[m];
            #pragma unroll
            for (int nt = 0; nt < 8; nt++) {
                int n = n0 + wn * 64 + nt * 8 + 2 * tig;
                float v0 = acc[mt][nt][rr * 2 + 0] + bi;
                float v1 = acc[mt][nt][rr * 2 + 1] + bi;
                if (rb) {
                    v0 += rb[(size_t)m * T + n];
                    v1 += rb[(size_t)m * T + n + 1];
                }
                *(float2*)&outb[(size_t)m * T + n] = make_float2(v0, v1);
            }
        }
    }
}

// ---------------------------------------------------------------------------
// Flash attention: bf16 m16n8k16, 128-wide key tiles (8 iters), 2 CTAs/SM,
// register-resident P (S-accumulator fragments feed PV directly),
// exp2-domain softmax (log2e folded into Q scale).
// SMEM (packed bf16x2 words, all fragment accesses conflict-free):
//   Qs[i][c2]  stride 36   (a-frag addr ≡ 4*gid+tig mod 32)
//   Ks[c2][j]  stride 136  (b-frag addr ≡ 8*tig+gid mod 32)
//   Vs[c][j2]  stride 68   (b-frag addr ≡ 4*gid+tig mod 32)
// ---------------------------------------------------------------------------
constexpr int QS_W = 36;
constexpr int KS_W = 136;
constexpr int VS_W = 68;

constexpr int ATTN_SMEM_WORDS = 128 * QS_W + 32 * KS_W + 64 * VS_W;  // 13312
constexpr int ATTN_SMEM_BYTES = ATTN_SMEM_WORDS * 4;                 // 53,248

__global__ __launch_bounds__(256, 2) void attn_kernel(
    const float* __restrict__ qkv, float* __restrict__ a_out)
{
    extern __shared__ uint32_t sm[];
    uint32_t* Qs = sm;                       // [i][c2]
    uint32_t* Ks = Qs + 128 * QS_W;          // [c2][j]
    uint32_t* Vs = Ks + 32 * KS_W;           // [c][j2]

    int blk = blockIdx.x;
    int qt = blk & 7, hh = blk >> 3;
    int b = hh >> 3, h = hh & 7;
    const float* qb = qkv + ((size_t)b * 1536 + h * 192) * Tn;
    const float* kb = qb + 64 * Tn;
    const float* vb = qb + 128 * Tn;
    int i0 = qt * 128;

    int tid = threadIdx.x, warp = tid >> 5, lane = tid & 31;
    int gid = lane >> 2, tig = lane & 3;
    int rA = warp * 16 + gid;        // first row; second is rA + 8

    // load Q packed, scaled by 0.125*log2e (exp2-domain softmax)
    const float qsc = 0.125f * LOG2E;
    #pragma unroll 4
    for (int e = tid; e < 32 * 128; e += 256) {
        int i = e & 127, c2 = e >> 7;
        float lo = qb[(size_t)(2 * c2    ) * Tn + i0 + i] * qsc;
        float hi = qb[(size_t)(2 * c2 + 1) * Tn + i0 + i] * qsc;
        Qs[i * QS_W + c2] = bfpack(lo, hi);
    }

    float mrow0 = -1e30f, mrow1 = -1e30f;
    float lrow0 = 0.f, lrow1 = 0.f;
    float oacc[8][4];
    #pragma unroll
    for (int nt = 0; nt < 8; nt++)
        #pragma unroll
        for (int q = 0; q < 4; q++) oacc[nt][q] = 0.f;

    for (int s0 = 0; s0 < Tn; s0 += 128) {
        __syncthreads();   // everyone done with previous K/V tile
        // stage K: Ks[c2][j], 128 keys
        #pragma unroll 4
        for (int e = tid; e < 32 * 128; e += 256) {
            int j = e & 127, c2 = e >> 7;
            Ks[c2 * KS_W + j] = bfpack(kb[(size_t)(2 * c2    ) * Tn + s0 + j],
                                       kb[(size_t)(2 * c2 + 1) * Tn + s0 + j]);
        }
        // stage V: Vs[c][j2]
        #pragma unroll 2
        for (int e = tid; e < 64 * 32; e += 256) {
            int j4 = e & 31, c = e >> 5;
            float4 v = *(const float4*)&vb[(size_t)c * Tn + s0 + 4 * j4];
            Vs[c * VS_W + 2 * j4    ] = bfpack(v.x, v.y);
            Vs[c * VS_W + 2 * j4 + 1] = bfpack(v.z, v.w);
        }
        __syncthreads();

        // ---- S = Q^T K : rows [warp*16,+16), cols 0..127 (log2 domain) ----
        float sacc[16][4];
        #pragma unroll
        for (int nt = 0; nt < 16; nt++)
            #pragma unroll
            for (int q = 0; q < 4; q++) sacc[nt][q] = 0.f;

        #pragma unroll
        for (int c2o = 0; c2o < 32; c2o += 8) {
            uint32_t a0 = Qs[(rA    ) * QS_W + c2o + tig    ];
            uint32_t a1 = Qs[(rA + 8) * QS_W + c2o + tig    ];
            uint32_t a2 = Qs[(rA    ) * QS_W + c2o + tig + 4];
            uint32_t a3 = Qs[(rA + 8) * QS_W + c2o + tig + 4];
            #pragma unroll
            for (int nt = 0; nt < 16; nt++) {
                uint32_t b0 = Ks[(c2o + tig    ) * KS_W + nt * 8 + gid];
                uint32_t b1 = Ks[(c2o + tig + 4) * KS_W + nt * 8 + gid];
                mma_bf16(sacc[nt], a0, a1, a2, a3, b0, b1);
            }
        }

        // ---- online softmax in exp2 domain ----
        float mx0 = -1e30f, mx1 = -1e30f;
        #pragma unroll
        for (int nt = 0; nt < 16; nt++) {
            mx0 = fmaxf(mx0, fmaxf(sacc[nt][0], sacc[nt][1]));
            mx1 = fmaxf(mx1, fmaxf(sacc[nt][2], sacc[nt][3]));
        }
        mx0 = fmaxf(mx0, __shfl_xor_sync(0xffffffffu, mx0, 1));
        mx0 = fmaxf(mx0, __shfl_xor_sync(0xffffffffu, mx0, 2));
        mx1 = fmaxf(mx1, __shfl_xor_sync(0xffffffffu, mx1, 1));
        mx1 = fmaxf(mx1, __shfl_xor_sync(0xffffffffu, mx1, 2));
        float mn0 = fmaxf(mrow0, mx0), mn1 = fmaxf(mrow1, mx1);
        float corr0 = exp2f(mrow0 - mn0), corr1 = exp2f(mrow1 - mn1);
        mrow0 = mn0; mrow1 = mn1;

        float rs0 = 0.f, rs1 = 0.f;
        #pragma unroll
        for (int nt = 0; nt < 16; nt++) {
            sacc[nt][0] = exp2f(sacc[nt][0] - mn0);
            sacc[nt][1] = exp2f(sacc[nt][1] - mn0);
            sacc[nt][2] = exp2f(sacc[nt][2] - mn1);
            sacc[nt][3] = exp2f(sacc[nt][3] - mn1);
            rs0 += sacc[nt][0] + sacc[nt][1];
            rs1 += sacc[nt][2] + sacc[nt][3];
        }
        rs0 += __shfl_xor_sync(0xffffffffu, rs0, 1);
        rs0 += __shfl_xor_sync(0xffffffffu, rs0, 2);
        rs1 += __shfl_xor_sync(0xffffffffu, rs1, 1);
        rs1 += __shfl_xor_sync(0xffffffffu, rs1, 2);
        lrow0 = lrow0 * corr0 + rs0;
        lrow1 = lrow1 * corr1 + rs1;
        #pragma unroll
        for (int nt = 0; nt < 8; nt++) {
            oacc[nt][0] *= corr0; oacc[nt][1] *= corr0;
            oacc[nt][2] *= corr1; oacc[nt][3] *= corr1;
        }

        // ---- O += P * V : P packed from sacc registers (no SMEM) ----
        #pragma unroll
        for (int kbk = 0; kbk < 8; kbk++) {
            uint32_t a0 = bfpack(sacc[2 * kbk    ][0], sacc[2 * kbk    ][1]);
            uint32_t a1 = bfpack(sacc[2 * kbk    ][2], sacc[2 * kbk    ][3]);
            uint32_t a2 = bfpack(sacc[2 * kbk + 1][0], sacc[2 * kbk + 1][1]);
            uint32_t a3 = bfpack(sacc[2 * kbk + 1][2], sacc[2 * kbk + 1][3]);
            #pragma unroll
            for (int nt = 0; nt < 8; nt++) {
                uint32_t b0 = Vs[(nt * 8 + gid) * VS_W + 8 * kbk + tig    ];
                uint32_t b1 = Vs[(nt * 8 + gid) * VS_W + 8 * kbk + tig + 4];
                mma_bf16(oacc[nt], a0, a1, a2, a3, b0, b1);
            }
        }
    }

    // epilogue: a[b][h*64+c][i0+i] = oacc / l
    float inv0 = 1.f / lrow0, inv1 = 1.f / lrow1;
    size_t obase = ((size_t)b * Cn + h * CH) * Tn + i0;
    #pragma unroll
    for (int nt = 0; nt < 8; nt++) {
        int c = nt * 8 + 2 * tig;
        a_out[obase + (size_t)(c    ) * Tn + rA    ] = oacc[nt][0] * inv0;
        a_out[obase + (size_t)(c + 1) * Tn + rA    ] = oacc[nt][1] * inv0;
        a_out[obase + (size_t)(c    ) * Tn + rA + 8] = oacc[nt][2] * inv1;
        a_out[obase + (size_t)(c + 1) * Tn + rA + 8] = oacc[nt][3] * inv1;
    }
}

// ---------------------------------------------------------------------------
extern "C" void kernel_launch(void* const* d_in, const int* in_sizes, int n_in,
                              void* d_out, int out_size)
{
    const float* x      = (const float*)d_in[0];
    const float* gamma  = (const float*)d_in[1];
    const float* beta   = (const float*)d_in[2];
    const float* w_qkv  = (const float*)d_in[3];
    const float* b_qkv  = (const float*)d_in[4];
    const float* w_proj = (const float*)d_in[5];
    const float* b_proj = (const float*)d_in[6];
    float* out = (float*)d_out;

    float *h_ptr, *qkv_ptr, *a_ptr;
    cudaGetSymbolAddress((void**)&h_ptr,   g_h);
    cudaGetSymbolAddress((void**)&qkv_ptr, g_qkv);
    cudaGetSymbolAddress((void**)&a_ptr,   g_a);

    cudaFuncSetAttribute(attn_kernel,
                         cudaFuncAttributeMaxDynamicSharedMemorySize,
                         ATTN_SMEM_BYTES);

    // 1. GroupNorm
    gn_kernel<<<Bn * NG, 256>>>(x, gamma, beta, h_ptr);

    // 2. QKV GEMM
    sgemm_bf16<<<dim3(Tn / 128, 1536 / 128, Bn), 256>>>(
        w_qkv, h_ptr, b_qkv, nullptr, qkv_ptr, 1536, Cn, Tn);

    // 3-5. spacers so ncu (-s 5 -c 1) captures attn_kernel as launch #6
    nop_kernel<<<1, 32>>>();
    nop_kernel<<<1, 32>>>();
    nop_kernel<<<1, 32>>>();

    // 6. Attention (bf16, register-P, 2 CTAs/SM, exp2 softmax)
    attn_kernel<<<Bn * NH * (Tn / 128), 256, ATTN_SMEM_BYTES>>>(qkv_ptr, a_ptr);

    // 7. Proj GEMM + bias + residual
    sgemm_bf16<<<dim3(Tn / 128, Cn / 128, Bn), 256>>>(
        w_proj, a_ptr, b_proj, x, out, Cn, Cn, Tn);
}